// round 1
// baseline (speedup 1.0000x reference)
#include <cuda_runtime.h>

// Problem constants
#define BSZ   32
#define TN    512
#define DN    256
#define FN    256
#define ROWS  (BSZ * TN)        // 16384
#define KSUM  768               // 3 * 256
#define MEL   2048
#define OUT_LR_ELEMS (BSZ * MEL * DN)   // 16777216

// ---- device scratch (no allocations allowed; __device__ globals are the sanctioned path) ----
__device__ float g_w1t[KSUM * FN];      // transposed conv1 weights [kk][f], kk = k*256 + d
__device__ float g_w2t[KSUM * FN];      // transposed conv2 weights
__device__ float g_h1[ROWS * FN];       // conv1 -> LN -> relu intermediate
__device__ int   g_map[BSZ * MEL];      // frame -> phoneme index (or -1)

// ============================================================
// Weight transpose: wT[(k*256+d)*256 + f] = w[f*768 + d*3 + k]
// ============================================================
__global__ void transpose_w_kernel(const float* __restrict__ w1,
                                   const float* __restrict__ w2) {
    int i = blockIdx.x * blockDim.x + threadIdx.x;
    if (i < KSUM * FN) {
        int kk = i / FN;
        int f  = i - kk * FN;
        int k  = kk >> 8;          // tap 0..2
        int d  = kk & 255;
        int src = f * KSUM + d * 3 + k;
        g_w1t[i] = w1[src];
        g_w2t[i] = w2[src];
    }
}

// ============================================================
// Per-batch inclusive scan of durations + scatter frame->phoneme map
// One block per batch, 512 threads.
// ============================================================
__global__ void build_map_kernel(const int* __restrict__ target) {
    __shared__ int s[TN];
    const int b = blockIdx.x;
    const int t = threadIdx.x;

    const int dur = target[b * TN + t];
    s[t] = dur;
    __syncthreads();

    // Hillis-Steele inclusive scan
    for (int off = 1; off < TN; off <<= 1) {
        int v = s[t];
        int u = (t >= off) ? s[t - off] : 0;
        __syncthreads();
        s[t] = v + u;
        __syncthreads();
    }

    const int end_   = s[t];
    const int start_ = end_ - dur;

    // init map to -1 (frames past total duration -> zeros)
    for (int m = t; m < MEL; m += TN) g_map[b * MEL + m] = -1;
    __syncthreads();

    if (start_ < MEL) {
        int e = end_ < MEL ? end_ : MEL;
        for (int m = start_; m < e; m++) g_map[b * MEL + m] = t;
    }
}

// ============================================================
// LR gather: out[b, m, :] = (map >= 0) ? x[b, map, :] : 0
// One warp per output row (256 floats = 2 x float4 per lane).
// ============================================================
__global__ void gather_kernel(const float* __restrict__ x,
                              float* __restrict__ out) {
    const int warp = threadIdx.x >> 5;
    const int lane = threadIdx.x & 31;
    const int row  = blockIdx.x * 8 + warp;        // 0 .. BSZ*MEL-1
    const int b    = row >> 11;                    // / MEL
    const int t    = g_map[row];

    float4 v0, v1;
    if (t >= 0) {
        const float4* src = (const float4*)(x + (size_t)(b * TN + t) * DN);
        v0 = src[lane];
        v1 = src[lane + 32];
    } else {
        v0 = make_float4(0.f, 0.f, 0.f, 0.f);
        v1 = v0;
    }
    float4* dst = (float4*)(out + (size_t)row * DN);
    dst[lane]      = v0;
    dst[lane + 32] = v1;
}

// ============================================================
// Fused conv(K=3) GEMM + bias + LayerNorm + ReLU (+ optional linear->dp_out)
//   Out[r, f] = sum_{k,d} In[r+k-1, d] * wT[(k*256+d)*256 + f]
// Block tile: 64 rows x 256 cols (full feature dim), BK = 16.
// 256 threads; warp ty owns rows ty*8..ty*8+7 completely -> LN is warp-local.
// FINAL=false: write LN/relu result to out ([ROWS, 256]).
// FINAL=true : epilogue dot with lin_w, write dp scalar per row to out.
// ============================================================
__device__ __forceinline__ float warp_sum(float v) {
    v += __shfl_xor_sync(0xffffffffu, v, 16);
    v += __shfl_xor_sync(0xffffffffu, v, 8);
    v += __shfl_xor_sync(0xffffffffu, v, 4);
    v += __shfl_xor_sync(0xffffffffu, v, 2);
    v += __shfl_xor_sync(0xffffffffu, v, 1);
    return v;
}

template <bool FINAL>
__global__ void __launch_bounds__(256)
conv_ln_kernel(const float* __restrict__ in,
               const float* __restrict__ wT,
               const float* __restrict__ bias,
               const float* __restrict__ gamma,
               const float* __restrict__ beta,
               const float* __restrict__ lw,
               const float* __restrict__ lb,
               float* __restrict__ out) {
    __shared__ float As[16][68];    // [k-slice][row], padded
    __shared__ float Bs[16][264];   // [k-slice][col], padded

    const int tid = threadIdx.x;
    const int ty  = tid >> 5;       // warp id 0..7 -> row group
    const int tx  = tid & 31;       // lane    -> col group
    const int rowBase = blockIdx.x * 64;

    float acc[8][8];
#pragma unroll
    for (int i = 0; i < 8; i++)
#pragma unroll
        for (int j = 0; j < 8; j++) acc[i][j] = 0.f;

    // A-load mapping: thread -> (row, 4 consecutive d)
    const int lrow = tid >> 2;          // 0..63
    const int lc4  = (tid & 3) * 4;     // 0,4,8,12
    // B-load mapping: thread -> (kk row, 16 consecutive cols)
    const int bkk  = tid >> 4;          // 0..15
    const int bc0  = (tid & 15) * 16;   // 0..240

    for (int kt = 0; kt < 48; kt++) {
        const int k  = kt >> 4;            // conv tap 0..2
        const int d0 = (kt & 15) << 4;     // d offset 0..240

        // ---- load A tile (64 rows x 16 d), conv shift + zero padding ----
        {
            const int gr   = rowBase + lrow;
            const int tpos = (gr & (TN - 1)) + k - 1;
            float4 v = make_float4(0.f, 0.f, 0.f, 0.f);
            if (tpos >= 0 && tpos < TN)
                v = *(const float4*)(in + (size_t)(gr + k - 1) * DN + d0 + lc4);
            As[lc4 + 0][lrow] = v.x;
            As[lc4 + 1][lrow] = v.y;
            As[lc4 + 2][lrow] = v.z;
            As[lc4 + 3][lrow] = v.w;
        }
        // ---- load B tile (16 kk x 256 f), fully coalesced from wT ----
        {
            const float* src = wT + (size_t)(k * DN + d0 + bkk) * FN + bc0;
            float4 v0 = *(const float4*)(src + 0);
            float4 v1 = *(const float4*)(src + 4);
            float4 v2 = *(const float4*)(src + 8);
            float4 v3 = *(const float4*)(src + 12);
            *(float4*)&Bs[bkk][bc0 + 0]  = v0;
            *(float4*)&Bs[bkk][bc0 + 4]  = v1;
            *(float4*)&Bs[bkk][bc0 + 8]  = v2;
            *(float4*)&Bs[bkk][bc0 + 12] = v3;
        }
        __syncthreads();

#pragma unroll
        for (int kk = 0; kk < 16; kk++) {
            float a[8], b[8];
            float4 t0;
            t0 = *(const float4*)&As[kk][ty * 8];
            a[0] = t0.x; a[1] = t0.y; a[2] = t0.z; a[3] = t0.w;
            t0 = *(const float4*)&As[kk][ty * 8 + 4];
            a[4] = t0.x; a[5] = t0.y; a[6] = t0.z; a[7] = t0.w;
            t0 = *(const float4*)&Bs[kk][tx * 8];
            b[0] = t0.x; b[1] = t0.y; b[2] = t0.z; b[3] = t0.w;
            t0 = *(const float4*)&Bs[kk][tx * 8 + 4];
            b[4] = t0.x; b[5] = t0.y; b[6] = t0.z; b[7] = t0.w;
#pragma unroll
            for (int i = 0; i < 8; i++)
#pragma unroll
                for (int j = 0; j < 8; j++)
                    acc[i][j] = fmaf(a[i], b[j], acc[i][j]);
        }
        __syncthreads();
    }

    // ---- epilogue: bias + LayerNorm + ReLU (+ linear) ----
    const int c0 = tx * 8;
    float bia[8], gam[8], bet[8], lwv[8];
#pragma unroll
    for (int j = 0; j < 8; j++) {
        bia[j] = bias[c0 + j];
        gam[j] = gamma[c0 + j];
        bet[j] = beta[c0 + j];
        if (FINAL) lwv[j] = lw[c0 + j];
    }
    const float lb0 = FINAL ? lb[0] : 0.f;

#pragma unroll
    for (int i = 0; i < 8; i++) {
        const int gr = rowBase + ty * 8 + i;
        float s = 0.f;
#pragma unroll
        for (int j = 0; j < 8; j++) {
            acc[i][j] += bia[j];
            s += acc[i][j];
        }
        s = warp_sum(s);
        const float mean = s * (1.f / 256.f);
        float q = 0.f;
#pragma unroll
        for (int j = 0; j < 8; j++) {
            float d = acc[i][j] - mean;
            q += d * d;
        }
        q = warp_sum(q);
        const float inv = rsqrtf(q * (1.f / 256.f) + 1e-5f);

        float v[8];
#pragma unroll
        for (int j = 0; j < 8; j++) {
            float z = (acc[i][j] - mean) * inv * gam[j] + bet[j];
            v[j] = fmaxf(z, 0.f);
        }

        if (!FINAL) {
            float4* o = (float4*)(out + (size_t)gr * FN + c0);
            o[0] = make_float4(v[0], v[1], v[2], v[3]);
            o[1] = make_float4(v[4], v[5], v[6], v[7]);
        } else {
            float p = 0.f;
#pragma unroll
            for (int j = 0; j < 8; j++) p = fmaf(v[j], lwv[j], p);
            p = warp_sum(p);
            if (tx == 0) out[gr] = p + lb0;
        }
    }
}

// ============================================================
// launch
// ============================================================
extern "C" void kernel_launch(void* const* d_in, const int* in_sizes, int n_in,
                              void* d_out, int out_size) {
    const float* x   = (const float*)d_in[0];
    const float* w1  = (const float*)d_in[1];
    const float* b1  = (const float*)d_in[2];
    const float* g1  = (const float*)d_in[3];
    const float* be1 = (const float*)d_in[4];
    const float* w2  = (const float*)d_in[5];
    const float* b2  = (const float*)d_in[6];
    const float* g2  = (const float*)d_in[7];
    const float* be2 = (const float*)d_in[8];
    const float* lw  = (const float*)d_in[9];
    const float* lb  = (const float*)d_in[10];
    const int* target = (const int*)d_in[11];
    float* out = (float*)d_out;

    float *w1t, *w2t, *h1;
    cudaGetSymbolAddress((void**)&w1t, g_w1t);
    cudaGetSymbolAddress((void**)&w2t, g_w2t);
    cudaGetSymbolAddress((void**)&h1,  g_h1);

    // weight transpose (needed before conv GEMMs)
    transpose_w_kernel<<<(KSUM * FN + 255) / 256, 256>>>(w1, w2);

    // LR path: scan+map, then gather into d_out[0 .. B*M*D)
    build_map_kernel<<<BSZ, TN>>>(target);
    gather_kernel<<<(BSZ * MEL) / 8, 256>>>(x, out);

    // duration predictor: conv1+LN+relu -> h1 ; conv2+LN+relu+linear -> dp_out
    conv_ln_kernel<false><<<ROWS / 64, 256>>>(x,  w1t, b1, g1, be1, nullptr, nullptr, h1);
    conv_ln_kernel<true ><<<ROWS / 64, 256>>>(h1, w2t, b2, g2, be2, lw, lb, out + OUT_LR_ELEMS);
}

// round 4
// speedup vs baseline: 1.5433x; 1.5433x over previous
#include <cuda_runtime.h>
#include <cuda_bf16.h>
#include <mma.h>
#include <cstdint>

using namespace nvcuda;

// Problem constants
#define BSZ   32
#define TN    512
#define DN    256
#define FN    256
#define ROWS  (BSZ * TN)        // 16384
#define KSUM  768               // 3 * 256
#define MEL   2048
#define OUT_LR_ELEMS (BSZ * MEL * DN)   // 16777216

// GEMM tiling (tf32: fragments are m16n16k8)
#define BM       128
#define BK       32
#define LDAB     40              // padded leading dim (floats)
#define NCHUNK   24              // 768 / 32
#define NTHREADS 512
#define STAGE_LD 264             // 256 + 8 padding

// ---------------- device scratch (fp32, tf32-rounded where noted) ----------------
__device__ float g_xt[ROWS * DN];       // x rounded to tf32
__device__ float g_h1[ROWS * FN];       // conv1 out (LN+relu), tf32-rounded
__device__ float g_w1t[KSUM * FN];      // w transposed [f][kk], kk=k*256+d, tf32-rounded
__device__ float g_w2t[KSUM * FN];
__device__ int   g_map[BSZ * MEL];

// ---------------- smem layout (bytes) ----------------
// A bufs: 2 x (128 x 40 x 4) = 40960   at 0
// B bufs: 2 x (256 x 40 x 4) = 81920   at 40960   (end 122880)
// stage : 128 x 264 x 4      = 135168  at 0 (UNION with tiles; used post-MMA)
// params: 4 x 1024 at 135168
#define OFF_A      0
#define OFF_B      40960
#define OFF_STAGE  0
#define OFF_BIAS   135168
#define OFF_GAMMA  (OFF_BIAS  + 1024)
#define OFF_BETA   (OFF_GAMMA + 1024)
#define OFF_LW     (OFF_BETA  + 1024)
#define SMEM_BYTES (OFF_LW + 1024)      // 139264

__device__ __forceinline__ float warp_sum(float v) {
    v += __shfl_xor_sync(0xffffffffu, v, 16);
    v += __shfl_xor_sync(0xffffffffu, v, 8);
    v += __shfl_xor_sync(0xffffffffu, v, 4);
    v += __shfl_xor_sync(0xffffffffu, v, 2);
    v += __shfl_xor_sync(0xffffffffu, v, 1);
    return v;
}

// ============================================================
// Conversion kernels (round-to-nearest tf32 once, up front)
// ============================================================
__global__ void convert_w_kernel(const float* __restrict__ w1,
                                 const float* __restrict__ w2) {
    int i = blockIdx.x * blockDim.x + threadIdx.x;
    if (i < KSUM * FN) {
        int f  = i / KSUM;
        int kk = i - f * KSUM;
        int k  = kk >> 8;
        int d  = kk & 255;
        int src = f * KSUM + d * 3 + k;       // w[f][d][k]
        g_w1t[i] = wmma::__float_to_tf32(w1[src]);
        g_w2t[i] = wmma::__float_to_tf32(w2[src]);
    }
}

__global__ void convert_x_kernel(const float* __restrict__ x) {
    int i = blockIdx.x * blockDim.x + threadIdx.x;   // float4 units
    if (i < ROWS * DN / 4) {
        float4 v = ((const float4*)x)[i];
        v.x = wmma::__float_to_tf32(v.x);
        v.y = wmma::__float_to_tf32(v.y);
        v.z = wmma::__float_to_tf32(v.z);
        v.w = wmma::__float_to_tf32(v.w);
        ((float4*)g_xt)[i] = v;
    }
}

// ============================================================
// Per-batch scan + frame->phoneme map
// ============================================================
__global__ void build_map_kernel(const int* __restrict__ target) {
    __shared__ int s[TN];
    const int b = blockIdx.x;
    const int t = threadIdx.x;
    const int dur = target[b * TN + t];
    s[t] = dur;
    __syncthreads();
    for (int off = 1; off < TN; off <<= 1) {
        int v = s[t];
        int u = (t >= off) ? s[t - off] : 0;
        __syncthreads();
        s[t] = v + u;
        __syncthreads();
    }
    const int end_   = s[t];
    const int start_ = end_ - dur;
    for (int m = t; m < MEL; m += TN) g_map[b * MEL + m] = -1;
    __syncthreads();
    if (start_ < MEL) {
        int e = end_ < MEL ? end_ : MEL;
        for (int m = start_; m < e; m++) g_map[b * MEL + m] = t;
    }
}

// ============================================================
// LR gather (output 0; exact copy of x rows)
// ============================================================
__global__ void gather_kernel(const float* __restrict__ x,
                              float* __restrict__ out) {
    const int warp = threadIdx.x >> 5;
    const int lane = threadIdx.x & 31;
    const int row  = blockIdx.x * 8 + warp;
    const int b    = row >> 11;
    const int t    = g_map[row];
    float4 v0, v1;
    if (t >= 0) {
        const float4* src = (const float4*)(x + (size_t)(b * TN + t) * DN);
        v0 = src[lane];
        v1 = src[lane + 32];
    } else {
        v0 = make_float4(0.f, 0.f, 0.f, 0.f);
        v1 = v0;
    }
    float4* dst = (float4*)(out + (size_t)row * DN);
    dst[lane]      = v0;
    dst[lane + 32] = v1;
}

// ============================================================
// tf32 wmma conv GEMM: out[r, f] = sum_{k,d} in[r+k-1, d] * w[f][k*256+d]
// CTA: 512 threads (16 warps, 4x4), tile 128 rows x 256 cols, BK=32.
// Epilogue: bias + LayerNorm + ReLU (+ linear dot -> dp_out for FINAL).
// ============================================================
template <bool FINAL>
__global__ void __launch_bounds__(NTHREADS)
conv_wmma_kernel(const float* __restrict__ in,
                 const float* __restrict__ wt,
                 const float* __restrict__ bias,
                 const float* __restrict__ gamma,
                 const float* __restrict__ beta,
                 const float* __restrict__ lw,
                 const float* __restrict__ lb,
                 float* __restrict__ outh,
                 float* __restrict__ outf) {
    extern __shared__ char smem[];
    const int tid  = threadIdx.x;
    const int wid  = tid >> 5;
    const int lane = tid & 31;
    const int wm   = wid & 3;          // warp row group (0..3) -> 32 rows
    const int wn   = wid >> 2;         // warp col group (0..3) -> 64 cols
    const int rowBase = blockIdx.x * BM;

    // stage params
    if (tid < 256) {
        ((float*)(smem + OFF_BIAS))[tid]  = bias[tid];
        ((float*)(smem + OFF_GAMMA))[tid] = gamma[tid];
        ((float*)(smem + OFF_BETA))[tid]  = beta[tid];
        if (FINAL) ((float*)(smem + OFF_LW))[tid] = lw[tid];
    }

    wmma::fragment<wmma::accumulator, 16, 16, 8, float> acc[2][4];
#pragma unroll
    for (int mt = 0; mt < 2; mt++)
#pragma unroll
        for (int nt = 0; nt < 4; nt++) wmma::fill_fragment(acc[mt][nt], 0.f);

    // tile loader: A = 128x32 (conv-shifted input), B = 256x32 (weights)
    auto load_tiles = [&](int c) {
        const int buf = c & 1;
        char* As = smem + OFF_A + buf * (BM * LDAB * 4);
        char* Bs = smem + OFF_B + buf * (FN * LDAB * 4);
        const int k   = c >> 3;
        const int d0  = (c & 7) << 5;
        const int km1 = k - 1;
        {   // A: 1024 uint4 units = 128 rows x 8 segs -> 2 per thread
#pragma unroll
            for (int i = 0; i < 2; i++) {
                const int u   = i * NTHREADS + tid;
                const int row = u >> 3, seg = u & 7;
                const int gr  = rowBase + row;
                const int tpos = (gr & (TN - 1)) + km1;
                uint4 v = make_uint4(0u, 0u, 0u, 0u);
                if (tpos >= 0 && tpos < TN)
                    v = *(const uint4*)(in + (size_t)(gr + km1) * DN + d0 + seg * 4);
                *(uint4*)(As + row * (LDAB * 4) + seg * 16) = v;
            }
        }
#pragma unroll
        for (int i = 0; i < 4; i++) {   // B: 2048 uint4 units = 256 rows x 8 segs
            const int u = i * NTHREADS + tid;
            const int f = u >> 3, seg = u & 7;
            uint4 v = *(const uint4*)(wt + (size_t)f * KSUM + c * BK + seg * 4);
            *(uint4*)(Bs + f * (LDAB * 4) + seg * 16) = v;
        }
    };

    load_tiles(0);
    __syncthreads();

    for (int c = 0; c < NCHUNK; c++) {
        const int buf = c & 1;
        if (c + 1 < NCHUNK) load_tiles(c + 1);

        const float* As = (const float*)(smem + OFF_A + buf * (BM * LDAB * 4));
        const float* Bs = (const float*)(smem + OFF_B + buf * (FN * LDAB * 4));
#pragma unroll
        for (int ks = 0; ks < 4; ks++) {
            wmma::fragment<wmma::matrix_a, 16, 16, 8, wmma::precision::tf32, wmma::row_major> af[2];
            wmma::fragment<wmma::matrix_b, 16, 16, 8, wmma::precision::tf32, wmma::col_major> bf[4];
#pragma unroll
            for (int mt = 0; mt < 2; mt++)
                wmma::load_matrix_sync(af[mt], As + (wm * 32 + mt * 16) * LDAB + ks * 8, LDAB);
#pragma unroll
            for (int nt = 0; nt < 4; nt++)
                wmma::load_matrix_sync(bf[nt], Bs + (wn * 64 + nt * 16) * LDAB + ks * 8, LDAB);
#pragma unroll
            for (int mt = 0; mt < 2; mt++)
#pragma unroll
                for (int nt = 0; nt < 4; nt++)
                    wmma::mma_sync(acc[mt][nt], af[mt], bf[nt], acc[mt][nt]);
        }
        __syncthreads();
    }

    // ---- stage accumulators to smem (union over tiles) ----
    float* stage = (float*)(smem + OFF_STAGE);
#pragma unroll
    for (int mt = 0; mt < 2; mt++)
#pragma unroll
        for (int nt = 0; nt < 4; nt++)
            wmma::store_matrix_sync(stage + (wm * 32 + mt * 16) * STAGE_LD + wn * 64 + nt * 16,
                                    acc[mt][nt], STAGE_LD, wmma::mem_row_major);
    __syncthreads();

    // ---- epilogue: each of 16 warps owns 8 rows; lane owns 8 cols ----
    const float* sb_bias = (const float*)(smem + OFF_BIAS);
    const float* sb_g    = (const float*)(smem + OFF_GAMMA);
    const float* sb_b    = (const float*)(smem + OFF_BETA);
    const float* sb_lw   = (const float*)(smem + OFF_LW);
    const int c0 = lane * 8;

    float bia[8], gam[8], bet[8], lwv[8];
#pragma unroll
    for (int j = 0; j < 8; j++) {
        bia[j] = sb_bias[c0 + j];
        gam[j] = sb_g[c0 + j];
        bet[j] = sb_b[c0 + j];
        if (FINAL) lwv[j] = sb_lw[c0 + j];
    }
    const float lb0 = FINAL ? __ldg(lb) : 0.f;

#pragma unroll
    for (int i = 0; i < 8; i++) {
        const int row = wid * 8 + i;
        const int gr  = rowBase + row;
        float v[8];
        float s = 0.f;
#pragma unroll
        for (int j = 0; j < 8; j++) {
            v[j] = stage[row * STAGE_LD + c0 + j] + bia[j];
            s += v[j];
        }
        s = warp_sum(s);
        const float mean = s * (1.f / 256.f);
        float q = 0.f;
#pragma unroll
        for (int j = 0; j < 8; j++) {
            float d = v[j] - mean;
            q += d * d;
        }
        q = warp_sum(q);
        const float inv = rsqrtf(q * (1.f / 256.f) + 1e-5f);

        if (!FINAL) {
            float hv[8];
#pragma unroll
            for (int j = 0; j < 8; j++) {
                float z = (v[j] - mean) * inv * gam[j] + bet[j];
                hv[j] = wmma::__float_to_tf32(fmaxf(z, 0.f));   // tf32-round for next GEMM
            }
            float4* o = (float4*)(outh + (size_t)gr * FN + c0);
            o[0] = make_float4(hv[0], hv[1], hv[2], hv[3]);
            o[1] = make_float4(hv[4], hv[5], hv[6], hv[7]);
        } else {
            float p = 0.f;
#pragma unroll
            for (int j = 0; j < 8; j++) {
                float z = (v[j] - mean) * inv * gam[j] + bet[j];
                p = fmaf(fmaxf(z, 0.f), lwv[j], p);
            }
            p = warp_sum(p);
            if (lane == 0) outf[gr] = p + lb0;
        }
    }
}

// ============================================================
// launch
// ============================================================
extern "C" void kernel_launch(void* const* d_in, const int* in_sizes, int n_in,
                              void* d_out, int out_size) {
    const float* x   = (const float*)d_in[0];
    const float* w1  = (const float*)d_in[1];
    const float* b1  = (const float*)d_in[2];
    const float* g1  = (const float*)d_in[3];
    const float* be1 = (const float*)d_in[4];
    const float* w2  = (const float*)d_in[5];
    const float* b2  = (const float*)d_in[6];
    const float* g2  = (const float*)d_in[7];
    const float* be2 = (const float*)d_in[8];
    const float* lw  = (const float*)d_in[9];
    const float* lb  = (const float*)d_in[10];
    const int* target = (const int*)d_in[11];
    float* out = (float*)d_out;

    float *xt, *h1, *w1t, *w2t;
    cudaGetSymbolAddress((void**)&xt,  g_xt);
    cudaGetSymbolAddress((void**)&h1,  g_h1);
    cudaGetSymbolAddress((void**)&w1t, g_w1t);
    cudaGetSymbolAddress((void**)&w2t, g_w2t);

    cudaFuncSetAttribute(conv_wmma_kernel<false>,
                         cudaFuncAttributeMaxDynamicSharedMemorySize, SMEM_BYTES);
    cudaFuncSetAttribute(conv_wmma_kernel<true>,
                         cudaFuncAttributeMaxDynamicSharedMemorySize, SMEM_BYTES);

    convert_w_kernel<<<(KSUM * FN + 255) / 256, 256>>>(w1, w2);
    convert_x_kernel<<<(ROWS * DN / 4 + 255) / 256, 256>>>(x);

    build_map_kernel<<<BSZ, TN>>>(target);
    gather_kernel<<<(BSZ * MEL) / 8, 256>>>(x, out);

    conv_wmma_kernel<false><<<ROWS / BM, NTHREADS, SMEM_BYTES>>>(
        xt, w1t, b1, g1, be1, nullptr, nullptr, h1, nullptr);
    conv_wmma_kernel<true><<<ROWS / BM, NTHREADS, SMEM_BYTES>>>(
        h1, w2t, b2, g2, be2, lw, lb, nullptr, out + OUT_LR_ELEMS);
}

// round 5
// speedup vs baseline: 1.8909x; 1.2252x over previous
#include <cuda_runtime.h>
#include <cuda_bf16.h>
#include <mma.h>
#include <cstdint>

using namespace nvcuda;

// Problem constants
#define BSZ   32
#define TN    512
#define DN    256
#define FN    256
#define ROWS  (BSZ * TN)        // 16384
#define KSUM  768               // 3 * 256
#define MEL   2048
#define OUT_LR_ELEMS (BSZ * MEL * DN)   // 16777216

// GEMM tiling (tf32 m16n16k8 fragments), warp tile 64x64
#define BM       128
#define BK       32
#define LDAB     40              // padded leading dim (floats); 160B rows
#define NCHUNK   24              // 768 / 32
#define NTHREADS 256
#define STAGE_LD 264             // 256 + 8 padding

// ---------------- device scratch (fp32, tf32-rounded) ----------------
__device__ float g_xt[ROWS * DN];       // x rounded to tf32 (RN)
__device__ float g_h1[ROWS * FN];       // conv1 out (LN+relu), tf32-rounded
__device__ float g_w1t[KSUM * FN];      // w transposed [f][kk], kk=k*256+d
__device__ float g_w2t[KSUM * FN];
__device__ int   g_map[BSZ * MEL];

// ---------------- smem layout (bytes) ----------------
#define OFF_A      0                      // 2 x 128 x 40 x 4 = 40960
#define OFF_B      40960                  // 2 x 256 x 40 x 4 = 81920 (end 122880)
#define OFF_STAGE  0                      // 128 x 264 x 4 = 135168 (UNION with tiles)
#define OFF_BIAS   135168
#define OFF_GAMMA  (OFF_BIAS  + 1024)
#define OFF_BETA   (OFF_GAMMA + 1024)
#define OFF_LW     (OFF_BETA  + 1024)
#define SMEM_BYTES (OFF_LW + 1024)        // 139264

__device__ __forceinline__ float warp_sum(float v) {
    v += __shfl_xor_sync(0xffffffffu, v, 16);
    v += __shfl_xor_sync(0xffffffffu, v, 8);
    v += __shfl_xor_sync(0xffffffffu, v, 4);
    v += __shfl_xor_sync(0xffffffffu, v, 2);
    v += __shfl_xor_sync(0xffffffffu, v, 1);
    return v;
}

__device__ __forceinline__ void cp16(uint32_t dst, const void* src, int szbytes) {
    asm volatile("cp.async.ca.shared.global [%0], [%1], 16, %2;"
                 :: "r"(dst), "l"(src), "r"(szbytes));
}

// ============================================================
// Conversion kernels (RN tf32 rounding, once)
// ============================================================
__global__ void convert_w_kernel(const float* __restrict__ w1,
                                 const float* __restrict__ w2) {
    int i = blockIdx.x * blockDim.x + threadIdx.x;
    if (i < KSUM * FN) {
        int f  = i / KSUM;
        int kk = i - f * KSUM;
        int k  = kk >> 8;
        int d  = kk & 255;
        int src = f * KSUM + d * 3 + k;       // w[f][d][k]
        g_w1t[i] = wmma::__float_to_tf32(w1[src]);
        g_w2t[i] = wmma::__float_to_tf32(w2[src]);
    }
}

__global__ void convert_x_kernel(const float* __restrict__ x) {
    int i = blockIdx.x * blockDim.x + threadIdx.x;   // float4 units
    if (i < ROWS * DN / 4) {
        float4 v = ((const float4*)x)[i];
        v.x = wmma::__float_to_tf32(v.x);
        v.y = wmma::__float_to_tf32(v.y);
        v.z = wmma::__float_to_tf32(v.z);
        v.w = wmma::__float_to_tf32(v.w);
        ((float4*)g_xt)[i] = v;
    }
}

// ============================================================
// Per-batch scan + frame->phoneme map
// ============================================================
__global__ void build_map_kernel(const int* __restrict__ target) {
    __shared__ int s[TN];
    const int b = blockIdx.x;
    const int t = threadIdx.x;
    const int dur = target[b * TN + t];
    s[t] = dur;
    __syncthreads();
    for (int off = 1; off < TN; off <<= 1) {
        int v = s[t];
        int u = (t >= off) ? s[t - off] : 0;
        __syncthreads();
        s[t] = v + u;
        __syncthreads();
    }
    const int end_   = s[t];
    const int start_ = end_ - dur;
    for (int m = t; m < MEL; m += TN) g_map[b * MEL + m] = -1;
    __syncthreads();
    if (start_ < MEL) {
        int e = end_ < MEL ? end_ : MEL;
        for (int m = start_; m < e; m++) g_map[b * MEL + m] = t;
    }
}

// ============================================================
// LR gather (output 0; exact row copy of x)
// ============================================================
__global__ void gather_kernel(const float* __restrict__ x,
                              float* __restrict__ out) {
    const int warp = threadIdx.x >> 5;
    const int lane = threadIdx.x & 31;
    const int row  = blockIdx.x * 8 + warp;
    const int b    = row >> 11;
    const int t    = g_map[row];
    float4 v0, v1;
    if (t >= 0) {
        const float4* src = (const float4*)(x + (size_t)(b * TN + t) * DN);
        v0 = src[lane];
        v1 = src[lane + 32];
    } else {
        v0 = make_float4(0.f, 0.f, 0.f, 0.f);
        v1 = v0;
    }
    float4* dst = (float4*)(out + (size_t)row * DN);
    dst[lane]      = v0;
    dst[lane + 32] = v1;
}

// ============================================================
// tf32 wmma conv GEMM: out[r, f] = sum_{k,d} in[r+k-1, d] * w[f][k*256+d]
// CTA: 256 threads, 8 warps (2x4), warp tile 64x64, BK=32, cp.async 2-stage.
// Epilogue: bias + LayerNorm + ReLU (+ linear dot -> dp_out for FINAL).
// ============================================================
template <bool FINAL>
__global__ void __launch_bounds__(NTHREADS)
conv_wmma_kernel(const float* __restrict__ in,
                 const float* __restrict__ wt,
                 const float* __restrict__ bias,
                 const float* __restrict__ gamma,
                 const float* __restrict__ beta,
                 const float* __restrict__ lw,
                 const float* __restrict__ lb,
                 float* __restrict__ outh,
                 float* __restrict__ outf) {
    extern __shared__ char smem[];
    const uint32_t sbase = (uint32_t)__cvta_generic_to_shared(smem);
    const int tid  = threadIdx.x;
    const int wid  = tid >> 5;
    const int lane = tid & 31;
    const int wm   = wid & 1;          // warp row group (0..1) -> 64 rows
    const int wn   = wid >> 1;         // warp col group (0..3) -> 64 cols
    const int rowBase = blockIdx.x * BM;

    // stage params
    ((float*)(smem + OFF_BIAS))[tid]  = bias[tid];
    ((float*)(smem + OFF_GAMMA))[tid] = gamma[tid];
    ((float*)(smem + OFF_BETA))[tid]  = beta[tid];
    if (FINAL) ((float*)(smem + OFF_LW))[tid] = lw[tid];

    wmma::fragment<wmma::accumulator, 16, 16, 8, float> acc[4][4];
#pragma unroll
    for (int mt = 0; mt < 4; mt++)
#pragma unroll
        for (int nt = 0; nt < 4; nt++) wmma::fill_fragment(acc[mt][nt], 0.f);

    // cp.async tile loader: A = 128x32 (conv-shifted), B = 256x32 (weights)
    auto load_tiles = [&](int c) {
        const int buf = c & 1;
        const uint32_t As = sbase + OFF_A + buf * (BM * LDAB * 4);
        const uint32_t Bs = sbase + OFF_B + buf * (FN * LDAB * 4);
        const int k   = c >> 3;
        const int d0  = (c & 7) << 5;
        const int km1 = k - 1;
#pragma unroll
        for (int i = 0; i < 4; i++) {      // A: 1024 16B units
            const int u   = i * NTHREADS + tid;
            const int row = u >> 3, seg = u & 7;
            const int gr  = rowBase + row;
            const int tpos = (gr & (TN - 1)) + km1;
            const bool p = (tpos >= 0 && tpos < TN);
            const float* src = p ? (in + (size_t)(gr + km1) * DN + d0 + seg * 4) : in;
            cp16(As + row * (LDAB * 4) + seg * 16, src, p ? 16 : 0);
        }
#pragma unroll
        for (int i = 0; i < 8; i++) {      // B: 2048 16B units
            const int u = i * NTHREADS + tid;
            const int f = u >> 3, seg = u & 7;
            cp16(Bs + f * (LDAB * 4) + seg * 16,
                 wt + (size_t)f * KSUM + c * BK + seg * 4, 16);
        }
        asm volatile("cp.async.commit_group;" ::: "memory");
    };

    load_tiles(0);

    for (int c = 0; c < NCHUNK; c++) {
        const int buf = c & 1;
        if (c + 1 < NCHUNK) {
            load_tiles(c + 1);
            asm volatile("cp.async.wait_group 1;" ::: "memory");
        } else {
            asm volatile("cp.async.wait_group 0;" ::: "memory");
        }
        __syncthreads();

        const float* As = (const float*)(smem + OFF_A + buf * (BM * LDAB * 4));
        const float* Bs = (const float*)(smem + OFF_B + buf * (FN * LDAB * 4));
#pragma unroll
        for (int ks = 0; ks < 4; ks++) {
            wmma::fragment<wmma::matrix_a, 16, 16, 8, wmma::precision::tf32, wmma::row_major> af[4];
            wmma::fragment<wmma::matrix_b, 16, 16, 8, wmma::precision::tf32, wmma::col_major> bf[4];
#pragma unroll
            for (int mt = 0; mt < 4; mt++)
                wmma::load_matrix_sync(af[mt], As + (wm * 64 + mt * 16) * LDAB + ks * 8, LDAB);
#pragma unroll
            for (int nt = 0; nt < 4; nt++)
                wmma::load_matrix_sync(bf[nt], Bs + (wn * 64 + nt * 16) * LDAB + ks * 8, LDAB);
#pragma unroll
            for (int mt = 0; mt < 4; mt++)
#pragma unroll
                for (int nt = 0; nt < 4; nt++)
                    wmma::mma_sync(acc[mt][nt], af[mt], bf[nt], acc[mt][nt]);
        }
        __syncthreads();
    }

    // ---- stage accumulators to smem (union over tiles) ----
    float* stage = (float*)(smem + OFF_STAGE);
#pragma unroll
    for (int mt = 0; mt < 4; mt++)
#pragma unroll
        for (int nt = 0; nt < 4; nt++)
            wmma::store_matrix_sync(stage + (wm * 64 + mt * 16) * STAGE_LD + wn * 64 + nt * 16,
                                    acc[mt][nt], STAGE_LD, wmma::mem_row_major);
    __syncthreads();

    // ---- epilogue: each of 8 warps owns 16 rows; lane owns 8 cols ----
    const float* sb_bias = (const float*)(smem + OFF_BIAS);
    const float* sb_g    = (const float*)(smem + OFF_GAMMA);
    const float* sb_b    = (const float*)(smem + OFF_BETA);
    const float* sb_lw   = (const float*)(smem + OFF_LW);
    const int c0 = lane * 8;

    float bia[8], gam[8], bet[8], lwv[8];
#pragma unroll
    for (int j = 0; j < 8; j++) {
        bia[j] = sb_bias[c0 + j];
        gam[j] = sb_g[c0 + j];
        bet[j] = sb_b[c0 + j];
        if (FINAL) lwv[j] = sb_lw[c0 + j];
    }
    const float lb0 = FINAL ? __ldg(lb) : 0.f;

#pragma unroll
    for (int i = 0; i < 16; i++) {
        const int row = wid * 16 + i;
        const int gr  = rowBase + row;
        float v[8];
        float s = 0.f;
#pragma unroll
        for (int j = 0; j < 8; j++) {
            v[j] = stage[row * STAGE_LD + c0 + j] + bia[j];
            s += v[j];
        }
        s = warp_sum(s);
        const float mean = s * (1.f / 256.f);
        float q = 0.f;
#pragma unroll
        for (int j = 0; j < 8; j++) {
            float d = v[j] - mean;
            q += d * d;
        }
        q = warp_sum(q);
        const float inv = rsqrtf(q * (1.f / 256.f) + 1e-5f);

        if (!FINAL) {
            float hv[8];
#pragma unroll
            for (int j = 0; j < 8; j++) {
                float z = (v[j] - mean) * inv * gam[j] + bet[j];
                hv[j] = wmma::__float_to_tf32(fmaxf(z, 0.f));   // RN round for next GEMM
            }
            float4* o = (float4*)(outh + (size_t)gr * FN + c0);
            o[0] = make_float4(hv[0], hv[1], hv[2], hv[3]);
            o[1] = make_float4(hv[4], hv[5], hv[6], hv[7]);
        } else {
            float p = 0.f;
#pragma unroll
            for (int j = 0; j < 8; j++) {
                float z = (v[j] - mean) * inv * gam[j] + bet[j];
                p = fmaf(fmaxf(z, 0.f), lwv[j], p);
            }
            p = warp_sum(p);
            if (lane == 0) outf[gr] = p + lb0;
        }
    }
}

// ============================================================
// launch
// ============================================================
extern "C" void kernel_launch(void* const* d_in, const int* in_sizes, int n_in,
                              void* d_out, int out_size) {
    const float* x   = (const float*)d_in[0];
    const float* w1  = (const float*)d_in[1];
    const float* b1  = (const float*)d_in[2];
    const float* g1  = (const float*)d_in[3];
    const float* be1 = (const float*)d_in[4];
    const float* w2  = (const float*)d_in[5];
    const float* b2  = (const float*)d_in[6];
    const float* g2  = (const float*)d_in[7];
    const float* be2 = (const float*)d_in[8];
    const float* lw  = (const float*)d_in[9];
    const float* lb  = (const float*)d_in[10];
    const int* target = (const int*)d_in[11];
    float* out = (float*)d_out;

    float *xt, *h1, *w1t, *w2t;
    cudaGetSymbolAddress((void**)&xt,  g_xt);
    cudaGetSymbolAddress((void**)&h1,  g_h1);
    cudaGetSymbolAddress((void**)&w1t, g_w1t);
    cudaGetSymbolAddress((void**)&w2t, g_w2t);

    cudaFuncSetAttribute(conv_wmma_kernel<false>,
                         cudaFuncAttributeMaxDynamicSharedMemorySize, SMEM_BYTES);
    cudaFuncSetAttribute(conv_wmma_kernel<true>,
                         cudaFuncAttributeMaxDynamicSharedMemorySize, SMEM_BYTES);

    convert_w_kernel<<<(KSUM * FN + 255) / 256, 256>>>(w1, w2);
    convert_x_kernel<<<(ROWS * DN / 4 + 255) / 256, 256>>>(x);

    build_map_kernel<<<BSZ, TN>>>(target);
    gather_kernel<<<(BSZ * MEL) / 8, 256>>>(x, out);

    conv_wmma_kernel<false><<<ROWS / BM, NTHREADS, SMEM_BYTES>>>(
        xt, w1t, b1, g1, be1, nullptr, nullptr, h1, nullptr);
    conv_wmma_kernel<true><<<ROWS / BM, NTHREADS, SMEM_BYTES>>>(
        h1, w2t, b2, g2, be2, lw, lb, nullptr, out + OUT_LR_ELEMS);
}

// round 6
// speedup vs baseline: 5.3263x; 2.8168x over previous
#include <cuda_runtime.h>
#include <cuda_fp16.h>
#include <mma.h>
#include <cstdint>

using namespace nvcuda;

// Problem constants
#define BSZ   32
#define TN    512
#define DN    256
#define FN    256
#define ROWS  (BSZ * TN)        // 16384
#define KSUM  768               // 3 * 256
#define MEL   2048
#define OUT_LR_ELEMS (BSZ * MEL * DN)   // 16777216

// GEMM tiling (fp16 m16n16k16), warp tile 64x64, BK=64 halves, 3-stage cp.async
#define BM       128
#define BKH      64
#define LDA      72              // padded leading dim in halves (144B rows; LDSM bank-clean)
#define NCHUNK   12              // 768 / 64
#define NSTAGE   3
#define NTHREADS 256
#define STAGE_LD 264             // fp32 epilogue stage leading dim

// ---------------- device scratch ----------------
__device__ __half g_xh[ROWS * DN];      // x in fp16 (RN)
__device__ __half g_h1h[ROWS * FN];     // conv1 out (LN+relu), fp16 (RN)
__device__ __half g_w1h[KSUM * FN];     // w transposed [f][kk], kk=k*256+d, fp16
__device__ __half g_w2h[KSUM * FN];
__device__ int    g_map[BSZ * MEL];

// ---------------- smem layout (bytes) ----------------
// per stage: A = 128 x 144B = 18432 ; B = 256 x 144B = 36864 ; stride 55296
// 3 stages = 165888. fp32 epilogue stage (128 x 264 x 4 = 135168) UNIONs at 0.
#define STG_STRIDE 55296
#define OFF_B_IN_STG 18432
#define OFF_STAGE  0
#define OFF_BIAS   165888
#define OFF_GAMMA  (OFF_BIAS  + 1024)
#define OFF_BETA   (OFF_GAMMA + 1024)
#define OFF_LW     (OFF_BETA  + 1024)
#define SMEM_BYTES (OFF_LW + 1024)      // 169984

__device__ __forceinline__ float warp_sum(float v) {
    v += __shfl_xor_sync(0xffffffffu, v, 16);
    v += __shfl_xor_sync(0xffffffffu, v, 8);
    v += __shfl_xor_sync(0xffffffffu, v, 4);
    v += __shfl_xor_sync(0xffffffffu, v, 2);
    v += __shfl_xor_sync(0xffffffffu, v, 1);
    return v;
}

__device__ __forceinline__ void cp16(uint32_t dst, const void* src, int szbytes) {
    asm volatile("cp.async.ca.shared.global [%0], [%1], 16, %2;"
                 :: "r"(dst), "l"(src), "r"(szbytes));
}

// ============================================================
// Conversion kernels (RN fp16, once)
// ============================================================
__global__ void convert_w_kernel(const float* __restrict__ w1,
                                 const float* __restrict__ w2) {
    int i = blockIdx.x * blockDim.x + threadIdx.x;
    if (i < KSUM * FN) {
        int f  = i / KSUM;
        int kk = i - f * KSUM;
        int k  = kk >> 8;
        int d  = kk & 255;
        int src = f * KSUM + d * 3 + k;       // w[f][d][k]
        g_w1h[i] = __float2half_rn(w1[src]);
        g_w2h[i] = __float2half_rn(w2[src]);
    }
}

__global__ void convert_x_kernel(const float* __restrict__ x) {
    int i = blockIdx.x * blockDim.x + threadIdx.x;   // float4 -> half4 units
    if (i < ROWS * DN / 4) {
        float4 v = ((const float4*)x)[i];
        __half2 lo = __floats2half2_rn(v.x, v.y);
        __half2 hi = __floats2half2_rn(v.z, v.w);
        uint2 pk;
        pk.x = *(uint32_t*)&lo;
        pk.y = *(uint32_t*)&hi;
        ((uint2*)g_xh)[i] = pk;
    }
}

// ============================================================
// Per-batch scan + frame->phoneme map
// ============================================================
__global__ void build_map_kernel(const int* __restrict__ target) {
    __shared__ int s[TN];
    const int b = blockIdx.x;
    const int t = threadIdx.x;
    const int dur = target[b * TN + t];
    s[t] = dur;
    __syncthreads();
    for (int off = 1; off < TN; off <<= 1) {
        int v = s[t];
        int u = (t >= off) ? s[t - off] : 0;
        __syncthreads();
        s[t] = v + u;
        __syncthreads();
    }
    const int end_   = s[t];
    const int start_ = end_ - dur;
    for (int m = t; m < MEL; m += TN) g_map[b * MEL + m] = -1;
    __syncthreads();
    if (start_ < MEL) {
        int e = end_ < MEL ? end_ : MEL;
        for (int m = start_; m < e; m++) g_map[b * MEL + m] = t;
    }
}

// ============================================================
// LR gather (output 0; exact row copy of fp32 x)
// ============================================================
__global__ void gather_kernel(const float* __restrict__ x,
                              float* __restrict__ out) {
    const int warp = threadIdx.x >> 5;
    const int lane = threadIdx.x & 31;
    const int row  = blockIdx.x * 8 + warp;
    const int b    = row >> 11;
    const int t    = g_map[row];
    float4 v0, v1;
    if (t >= 0) {
        const float4* src = (const float4*)(x + (size_t)(b * TN + t) * DN);
        v0 = src[lane];
        v1 = src[lane + 32];
    } else {
        v0 = make_float4(0.f, 0.f, 0.f, 0.f);
        v1 = v0;
    }
    float4* dst = (float4*)(out + (size_t)row * DN);
    dst[lane]      = v0;
    dst[lane + 32] = v1;
}

// ============================================================
// fp16 wmma conv GEMM: out[r, f] = sum_{k,d} in[r+k-1, d] * w[f][k*256+d]
// 256 threads, 8 warps (2x4), warp tile 64x64, BK=64, 3-stage cp.async.
// Epilogue (fp32): bias + LayerNorm + ReLU (+ linear dot -> dp_out for FINAL).
// ============================================================
template <bool FINAL>
__global__ void __launch_bounds__(NTHREADS)
conv_wmma_kernel(const __half* __restrict__ in,
                 const __half* __restrict__ wh,
                 const float* __restrict__ bias,
                 const float* __restrict__ gamma,
                 const float* __restrict__ beta,
                 const float* __restrict__ lw,
                 const float* __restrict__ lb,
                 __half* __restrict__ outh,
                 float* __restrict__ outf) {
    extern __shared__ char smem[];
    const uint32_t sbase = (uint32_t)__cvta_generic_to_shared(smem);
    const int tid  = threadIdx.x;
    const int wid  = tid >> 5;
    const int lane = tid & 31;
    const int wm   = wid & 1;          // warp row group -> 64 rows
    const int wn   = wid >> 1;         // warp col group -> 64 cols
    const int rowBase = blockIdx.x * BM;

    // stage params
    ((float*)(smem + OFF_BIAS))[tid]  = bias[tid];
    ((float*)(smem + OFF_GAMMA))[tid] = gamma[tid];
    ((float*)(smem + OFF_BETA))[tid]  = beta[tid];
    if (FINAL) ((float*)(smem + OFF_LW))[tid] = lw[tid];

    wmma::fragment<wmma::accumulator, 16, 16, 16, float> acc[4][4];
#pragma unroll
    for (int mt = 0; mt < 4; mt++)
#pragma unroll
        for (int nt = 0; nt < 4; nt++) wmma::fill_fragment(acc[mt][nt], 0.f);

    // cp.async tile loader for chunk c into stage slot c%3.
    // A = 128 x 64 halves (conv-shifted input rows), B = 256 x 64 halves (weights)
    auto load_tiles = [&](int c) {
        const int slot = c % NSTAGE;
        const uint32_t As = sbase + slot * STG_STRIDE;
        const uint32_t Bs = As + OFF_B_IN_STG;
        const int k   = c >> 2;            // conv tap 0..2
        const int d0  = (c & 3) << 6;      // d offset 0..192
        const int km1 = k - 1;
#pragma unroll
        for (int i = 0; i < 4; i++) {      // A: 1024 16B units (8 halves each)
            const int u   = i * NTHREADS + tid;
            const int row = u >> 3, seg = u & 7;
            const int gr  = rowBase + row;
            const int tpos = (gr & (TN - 1)) + km1;
            const bool p = (tpos >= 0 && tpos < TN);
            const __half* src = p ? (in + (size_t)(gr + km1) * DN + d0 + seg * 8) : in;
            cp16(As + row * (LDA * 2) + seg * 16, src, p ? 16 : 0);
        }
#pragma unroll
        for (int i = 0; i < 8; i++) {      // B: 2048 16B units
            const int u = i * NTHREADS + tid;
            const int f = u >> 3, seg = u & 7;
            cp16(Bs + f * (LDA * 2) + seg * 16,
                 wh + (size_t)f * KSUM + c * BKH + seg * 8, 16);
        }
        asm volatile("cp.async.commit_group;" ::: "memory");
    };

    load_tiles(0);
    load_tiles(1);

    for (int c = 0; c < NCHUNK; c++) {
        // 1) ensure stage c has landed  2) barrier  3) prefetch c+2  4) compute c
        if (c < NCHUNK - 1) {
            asm volatile("cp.async.wait_group 1;" ::: "memory");
        } else {
            asm volatile("cp.async.wait_group 0;" ::: "memory");
        }
        __syncthreads();
        if (c + 2 < NCHUNK) load_tiles(c + 2);

        const int slot = c % NSTAGE;
        const __half* As = (const __half*)(smem + slot * STG_STRIDE);
        const __half* Bs = (const __half*)(smem + slot * STG_STRIDE + OFF_B_IN_STG);
#pragma unroll
        for (int ks = 0; ks < 4; ks++) {
            wmma::fragment<wmma::matrix_a, 16, 16, 16, __half, wmma::row_major> af[4];
            wmma::fragment<wmma::matrix_b, 16, 16, 16, __half, wmma::col_major> bf[4];
#pragma unroll
            for (int mt = 0; mt < 4; mt++)
                wmma::load_matrix_sync(af[mt], As + (wm * 64 + mt * 16) * LDA + ks * 16, LDA);
#pragma unroll
            for (int nt = 0; nt < 4; nt++)
                wmma::load_matrix_sync(bf[nt], Bs + (wn * 64 + nt * 16) * LDA + ks * 16, LDA);
#pragma unroll
            for (int mt = 0; mt < 4; mt++)
#pragma unroll
                for (int nt = 0; nt < 4; nt++)
                    wmma::mma_sync(acc[mt][nt], af[mt], bf[nt], acc[mt][nt]);
        }
    }
    __syncthreads();   // tiles dead; reuse smem as fp32 stage

    // ---- stage accumulators to smem ----
    float* stage = (float*)(smem + OFF_STAGE);
#pragma unroll
    for (int mt = 0; mt < 4; mt++)
#pragma unroll
        for (int nt = 0; nt < 4; nt++)
            wmma::store_matrix_sync(stage + (wm * 64 + mt * 16) * STAGE_LD + wn * 64 + nt * 16,
                                    acc[mt][nt], STAGE_LD, wmma::mem_row_major);
    __syncthreads();

    // ---- epilogue: each of 8 warps owns 16 rows; lane owns 8 cols ----
    const float* sb_bias = (const float*)(smem + OFF_BIAS);
    const float* sb_g    = (const float*)(smem + OFF_GAMMA);
    const float* sb_b    = (const float*)(smem + OFF_BETA);
    const float* sb_lw   = (const float*)(smem + OFF_LW);
    const int c0 = lane * 8;

    float bia[8], gam[8], bet[8], lwv[8];
#pragma unroll
    for (int j = 0; j < 8; j++) {
        bia[j] = sb_bias[c0 + j];
        gam[j] = sb_g[c0 + j];
        bet[j] = sb_b[c0 + j];
        if (FINAL) lwv[j] = sb_lw[c0 + j];
    }
    const float lb0 = FINAL ? __ldg(lb) : 0.f;

#pragma unroll
    for (int i = 0; i < 16; i++) {
        const int row = wid * 16 + i;
        const int gr  = rowBase + row;
        float v[8];
        float s = 0.f;
#pragma unroll
        for (int j = 0; j < 8; j++) {
            v[j] = stage[row * STAGE_LD + c0 + j] + bia[j];
            s += v[j];
        }
        s = warp_sum(s);
        const float mean = s * (1.f / 256.f);
        float q = 0.f;
#pragma unroll
        for (int j = 0; j < 8; j++) {
            float d = v[j] - mean;
            q += d * d;
        }
        q = warp_sum(q);
        const float inv = rsqrtf(q * (1.f / 256.f) + 1e-5f);

        if (!FINAL) {
            __half2 hv[4];
#pragma unroll
            for (int j = 0; j < 4; j++) {
                float za = (v[2*j]   - mean) * inv * gam[2*j]   + bet[2*j];
                float zb = (v[2*j+1] - mean) * inv * gam[2*j+1] + bet[2*j+1];
                hv[j] = __floats2half2_rn(fmaxf(za, 0.f), fmaxf(zb, 0.f));
            }
            *(uint4*)(outh + (size_t)gr * FN + c0) = *(uint4*)hv;
        } else {
            float p = 0.f;
#pragma unroll
            for (int j = 0; j < 8; j++) {
                float z = (v[j] - mean) * inv * gam[j] + bet[j];
                p = fmaf(fmaxf(z, 0.f), lwv[j], p);
            }
            p = warp_sum(p);
            if (lane == 0) outf[gr] = p + lb0;
        }
    }
}

// ============================================================
// launch
// ============================================================
extern "C" void kernel_launch(void* const* d_in, const int* in_sizes, int n_in,
                              void* d_out, int out_size) {
    const float* x   = (const float*)d_in[0];
    const float* w1  = (const float*)d_in[1];
    const float* b1  = (const float*)d_in[2];
    const float* g1  = (const float*)d_in[3];
    const float* be1 = (const float*)d_in[4];
    const float* w2  = (const float*)d_in[5];
    const float* b2  = (const float*)d_in[6];
    const float* g2  = (const float*)d_in[7];
    const float* be2 = (const float*)d_in[8];
    const float* lw  = (const float*)d_in[9];
    const float* lb  = (const float*)d_in[10];
    const int* target = (const int*)d_in[11];
    float* out = (float*)d_out;

    __half *xh, *h1h, *w1h, *w2h;
    cudaGetSymbolAddress((void**)&xh,  g_xh);
    cudaGetSymbolAddress((void**)&h1h, g_h1h);
    cudaGetSymbolAddress((void**)&w1h, g_w1h);
    cudaGetSymbolAddress((void**)&w2h, g_w2h);

    cudaFuncSetAttribute(conv_wmma_kernel<false>,
                         cudaFuncAttributeMaxDynamicSharedMemorySize, SMEM_BYTES);
    cudaFuncSetAttribute(conv_wmma_kernel<true>,
                         cudaFuncAttributeMaxDynamicSharedMemorySize, SMEM_BYTES);

    convert_w_kernel<<<(KSUM * FN + 255) / 256, 256>>>(w1, w2);
    convert_x_kernel<<<(ROWS * DN / 4 + 255) / 256, 256>>>(x);

    build_map_kernel<<<BSZ, TN>>>(target);
    gather_kernel<<<(BSZ * MEL) / 8, 256>>>(x, out);

    conv_wmma_kernel<false><<<ROWS / BM, NTHREADS, SMEM_BYTES>>>(
        xh, w1h, b1, g1, be1, nullptr, nullptr, h1h, nullptr);
    conv_wmma_kernel<true><<<ROWS / BM, NTHREADS, SMEM_BYTES>>>(
        h1h, w2h, b2, g2, be2, lw, lb, nullptr, out + OUT_LR_ELEMS);
}